// round 14
// baseline (speedup 1.0000x reference)
#include <cuda_runtime.h>
#include <cuda_fp16.h>
#include <cstdint>
#include <cstddef>

// ---------------------------------------------------------------------------
// HeteroMAGNet: fp16-native pipeline, cp.async pipelined GEMMs.
// R14: revert R13's BN=128 (2 blocks/SM killed overlap; occupancy > ILP here).
//      Back to BM128/BN64/4-blocks-per-SM, with KC 64->32 and a 3-stage
//      cp.async pipeline (2 chunk-loads always in flight, shorter prologue).
// ---------------------------------------------------------------------------

#define N_NODES 50000
#define N_AGENT 25000
#define E_EDGES 800000
#define SCAN_NB 49   // ceil(50000/1024)

// scratch (device globals: allocation-free)
__device__ __half g_xh[(size_t)N_NODES * 128];
__device__ __half g_th[(size_t)N_NODES * 128];
__device__ __half g_hh[(size_t)N_NODES * 128];
__device__ __half g_zwh[(size_t)N_NODES * 128];
__device__ __half g_xcath[(size_t)N_NODES * 384];
__device__ __half g_q1h[(size_t)N_AGENT * 256];
__device__ __half g_wt[204800];                  // all weights, fp16, [N][K]
__device__ float  g_dinv[N_NODES];
__device__ int    g_cnt[N_NODES];
__device__ int    g_fill[N_NODES];
__device__ int    g_rowstart[N_NODES + 1];
__device__ int    g_csrc[E_EDGES];
__device__ int    g_bsum[64];
__device__ int    g_boff[64];
__device__ int    g_is64;

// weight table offsets (halves) in g_wt
#define WT_E0W1 0        // K=128 N=128
#define WT_E1W1 16384    // K=64  N=128
#define WT_E0W2 24576    // K=128 N=128
#define WT_E1W2 40960    // K=128 N=128
#define WT_GW0  57344    // K=128 N=128
#define WT_GW1  73728
#define WT_GW2  90112
#define WT_AW1  106496   // K=384 N=256
#define WT_TOTAL 204800

// ---------------------------------------------------------------------------
// edge_index dtype detection (int64 vs harness-downcast int32)
// ---------------------------------------------------------------------------
__global__ void detect_k(const int* __restrict__ ei)
{
    int lane = threadIdx.x;
    int bad = 0;
    #pragma unroll
    for (int i = lane; i < 256; i += 32)
        if (ei[2 * i + 1] != 0) bad = 1;
    unsigned m = __ballot_sync(0xffffffffu, bad);
    if (lane == 0) g_is64 = (m == 0);
}

__device__ __forceinline__ int edge_at(const int* ei, int is64, int flat_idx)
{
    return is64 ? ei[2 * flat_idx] : ei[flat_idx];
}

// ---------------------------------------------------------------------------
// fp32 -> fp16 elementwise (n % 4 == 0)
// ---------------------------------------------------------------------------
__global__ void f2h_k(const float* __restrict__ src, __half* __restrict__ dst, int n)
{
    int i = (blockIdx.x * blockDim.x + threadIdx.x) * 4;
    if (i >= n) return;
    float4 v = *(const float4*)(src + i);
    __half2 h0 = __floats2half2_rn(v.x, v.y);
    __half2 h1 = __floats2half2_rn(v.z, v.w);
    *(uint2*)(dst + i) = make_uint2(*(uint32_t*)&h0, *(uint32_t*)&h1);
}

// ---------------------------------------------------------------------------
// all weights: transpose [K][N] -> [N][K] + convert to fp16, one kernel
// ---------------------------------------------------------------------------
__global__ void wconv_k(const float* __restrict__ w0, const float* __restrict__ w1,
                        const float* __restrict__ w2, const float* __restrict__ w3,
                        const float* __restrict__ w4, const float* __restrict__ w5,
                        const float* __restrict__ w6, const float* __restrict__ w7,
                        __half* __restrict__ wt)
{
    int i = blockIdx.x * blockDim.x + threadIdx.x;
    if (i >= WT_TOTAL) return;
    const float* w; int off, K, N;
    if      (i < WT_E1W1) { w = w0; off = WT_E0W1; K = 128; N = 128; }
    else if (i < WT_E0W2) { w = w1; off = WT_E1W1; K = 64;  N = 128; }
    else if (i < WT_E1W2) { w = w2; off = WT_E0W2; K = 128; N = 128; }
    else if (i < WT_GW0)  { w = w3; off = WT_E1W2; K = 128; N = 128; }
    else if (i < WT_GW1)  { w = w4; off = WT_GW0;  K = 128; N = 128; }
    else if (i < WT_GW2)  { w = w5; off = WT_GW1;  K = 128; N = 128; }
    else if (i < WT_AW1)  { w = w6; off = WT_GW2;  K = 128; N = 128; }
    else                  { w = w7; off = WT_AW1;  K = 384; N = 256; }
    int local = i - off;
    int n = local / K, k = local % K;
    wt[i] = __float2half(w[(size_t)k * N + n]);
}

// ---------------------------------------------------------------------------
// fp16 m16n8k16 MMA + ldmatrix + cp.async helpers
// ---------------------------------------------------------------------------
__device__ __forceinline__ void mma_f16(float& d0, float& d1, float& d2, float& d3,
                                        uint32_t a0, uint32_t a1, uint32_t a2, uint32_t a3,
                                        uint32_t b0, uint32_t b1)
{
    asm volatile(
        "mma.sync.aligned.m16n8k16.row.col.f32.f16.f16.f32 "
        "{%0,%1,%2,%3}, {%4,%5,%6,%7}, {%8,%9}, {%0,%1,%2,%3};\n"
        : "+f"(d0), "+f"(d1), "+f"(d2), "+f"(d3)
        : "r"(a0), "r"(a1), "r"(a2), "r"(a3), "r"(b0), "r"(b1));
}

__device__ __forceinline__ void ldsm4(uint32_t& r0, uint32_t& r1, uint32_t& r2, uint32_t& r3,
                                      uint32_t addr)
{
    asm volatile("ldmatrix.sync.aligned.m8n8.x4.shared.b16 {%0,%1,%2,%3}, [%4];"
                 : "=r"(r0), "=r"(r1), "=r"(r2), "=r"(r3) : "r"(addr));
}

__device__ __forceinline__ uint32_t smem_u32(const void* p)
{
    uint32_t a;
    asm("{ .reg .u64 t; cvta.to.shared.u64 t, %1; cvt.u32.u64 %0, t; }" : "=r"(a) : "l"(p));
    return a;
}

__device__ __forceinline__ void cp16(uint32_t dst, const void* src, int src_bytes)
{
    asm volatile("cp.async.cg.shared.global [%0], [%1], 16, %2;"
                 :: "r"(dst), "l"(src), "r"(src_bytes) : "memory");
}
#define CP_COMMIT() asm volatile("cp.async.commit_group;" ::: "memory")
#define CP_WAIT(n)  asm volatile("cp.async.wait_group %0;" :: "n"(n) : "memory")

// ---------------------------------------------------------------------------
// GEMM tile geometry: BM=128, BN=64, KC=32, 3-stage cp.async pipeline.
// smem stride 40 halves (80B): LDSM rows hit distinct 16B segs mod 128B.
// Stage = A[128][40] + B[64][40] halves = 15360B; 3 stages = 46080B dynamic.
// 256 thr, warps 4(m) x 2(n), warp tile 32x32.
// ---------------------------------------------------------------------------
#define KC      32
#define GSTR    40
#define STAGE_B 15360      // bytes per stage
#define AB_OFF  10240      // B tile offset within stage (128*40*2)
#define GSMEM   (3 * STAGE_B)

template <int EPI>
__device__ __forceinline__ void gemm_core(
    const __half* __restrict__ A, int lda, int bm, int rlimit,
    const __half* __restrict__ Bt, int bn, int K,
    const float* __restrict__ bias,
    __half* __restrict__ C, int ldc, int wlimit)
{
    extern __shared__ __half sm[];
    uint32_t sm_base = smem_u32(sm);
    int tid = threadIdx.x;
    int wid = tid >> 5, lane = tid & 31;
    int wm = wid >> 1, wn = wid & 1;
    int g = lane >> 2, q = lane & 3;

    float acc[2][4][4];
    #pragma unroll
    for (int i = 0; i < 2; i++)
        #pragma unroll
        for (int j = 0; j < 4; j++)
            #pragma unroll
            for (int k = 0; k < 4; k++) acc[i][j][k] = 0.f;

    // staging: A 128 rows x 4 vec16 (2/thread), B 64 rows x 4 vec16 (1/thread)
    auto load_stage = [&](int s, int k0) {
        uint32_t abase = sm_base + s * STAGE_B;
        #pragma unroll
        for (int j = 0; j < 2; j++) {
            int v = tid + 256 * j;
            int row = v >> 2, col = (v & 3) * 8;
            const __half* src = A + (size_t)(bm + row) * lda + k0 + col;
            cp16(abase + (uint32_t)(row * GSTR + col) * 2, src,
                 (bm + row < rlimit) ? 16 : 0);
        }
        {
            int row = tid >> 2, col = (tid & 3) * 8;
            const __half* src = Bt + (size_t)(bn + row) * K + k0 + col;
            cp16(abase + AB_OFF + (uint32_t)(row * GSTR + col) * 2, src, 16);
        }
        CP_COMMIT();
    };

    const int a_lrow = wm * 32 + (lane & 7) + ((lane >> 3) & 1) * 8;
    const int a_lcol = (lane >> 4) * 8;
    const int b_mat  = lane >> 3;
    const int b_lrow = wn * 32 + (b_mat >> 1) * 8 + (lane & 7);
    const int b_lcol = (b_mat & 1) * 8;

    const int NC = (K + KC - 1) / KC;   // >= 2 for all our K
    load_stage(0, 0);
    if (NC > 1) load_stage(1, KC);

    for (int c = 0; c < NC; c++) {
        if (c + 2 < NC) {
            load_stage((c + 2) % 3, (c + 2) * KC);
            CP_WAIT(2);
        } else if (c + 1 < NC) {
            CP_WAIT(1);
        } else {
            CP_WAIT(0);
        }
        __syncthreads();

        uint32_t a_base = sm_base + (c % 3) * STAGE_B;
        uint32_t b_base = a_base + AB_OFF;

        #pragma unroll
        for (int kk = 0; kk < KC; kk += 16) {
            uint32_t a[2][4], b[4][2];
            #pragma unroll
            for (int mt = 0; mt < 2; mt++) {
                uint32_t addr = a_base + (uint32_t)(((a_lrow + mt * 16) * GSTR) + kk + a_lcol) * 2;
                ldsm4(a[mt][0], a[mt][1], a[mt][2], a[mt][3], addr);
            }
            #pragma unroll
            for (int p = 0; p < 2; p++) {
                uint32_t addr = b_base + (uint32_t)(((b_lrow + p * 16) * GSTR) + kk + b_lcol) * 2;
                ldsm4(b[2*p][0], b[2*p][1], b[2*p+1][0], b[2*p+1][1], addr);
            }
            #pragma unroll
            for (int mt = 0; mt < 2; mt++)
                #pragma unroll
                for (int nt = 0; nt < 4; nt++)
                    mma_f16(acc[mt][nt][0], acc[mt][nt][1], acc[mt][nt][2], acc[mt][nt][3],
                            a[mt][0], a[mt][1], a[mt][2], a[mt][3],
                            b[nt][0], b[nt][1]);
        }
        __syncthreads();   // stage (c%3) reusable at iteration c+3's load (issued c+1)
    }

    #pragma unroll
    for (int mt = 0; mt < 2; mt++) {
        #pragma unroll
        for (int nt = 0; nt < 4; nt++) {
            int row0 = bm + wm * 32 + mt * 16 + g;
            int col  = bn + wn * 32 + nt * 8 + 2 * q;
            float bx = 0.f, by = 0.f;
            if (EPI >= 1) { bx = bias[col]; by = bias[col + 1]; }
            float v0 = acc[mt][nt][0] + bx, v1 = acc[mt][nt][1] + by;
            float v2 = acc[mt][nt][2] + bx, v3 = acc[mt][nt][3] + by;
            if (EPI == 2) {
                v0 = fmaxf(v0, 0.f); v1 = fmaxf(v1, 0.f);
                v2 = fmaxf(v2, 0.f); v3 = fmaxf(v3, 0.f);
            }
            if (row0 < wlimit)     *(__half2*)(C + (size_t)row0 * ldc + col)       = __floats2half2_rn(v0, v1);
            if (row0 + 8 < wlimit) *(__half2*)(C + (size_t)(row0 + 8) * ldc + col) = __floats2half2_rn(v2, v3);
        }
    }
}

template <int EPI>
__global__ __launch_bounds__(256)
void hgemm_k(const __half* __restrict__ A, int lda,
             const __half* __restrict__ Bt,
             int M, int N, int K,
             const float* __restrict__ bias,
             __half* __restrict__ C, int ldc)
{
    gemm_core<EPI>(A, lda, blockIdx.y * 128, M, Bt, blockIdx.x * 64, K, bias, C, ldc, M);
}

template <int EPI>
__global__ __launch_bounds__(256)
void hgemm2_k(const __half* __restrict__ A, int lda,
              const __half* __restrict__ Bt0, const __half* __restrict__ Bt1,
              int K0, int K1,
              const float* __restrict__ b0, const float* __restrict__ b1,
              __half* __restrict__ C, int ldc, int nby0, int M0, int M1)
{
    int by = blockIdx.y;
    if (by < nby0) {
        gemm_core<EPI>(A, lda, by * 128, M1, Bt0, blockIdx.x * 64, K0, b0, C, ldc, M0);
    } else {
        gemm_core<EPI>(A, lda, M0 + (by - nby0) * 128, M1, Bt1, blockIdx.x * 64, K1, b1, C, ldc, M1);
    }
}

// ---------------------------------------------------------------------------
// CSR build
// ---------------------------------------------------------------------------
__global__ void hist_k(const int* __restrict__ ei, int E, int* __restrict__ cnt)
{
    int e = blockIdx.x * blockDim.x + threadIdx.x;
    if (e >= E) return;
    int d = edge_at(ei, g_is64, E + e);
    if ((unsigned)d < (unsigned)N_NODES)
        atomicAdd(&cnt[d], 1);
}

__global__ void scan1_k(const int* __restrict__ cnt, int* __restrict__ rowstart,
                        int* __restrict__ bsum, float* __restrict__ dinv, int N)
{
    __shared__ int wsum[32];
    int tid = threadIdx.x, lane = tid & 31, wid = tid >> 5;
    int i = blockIdx.x * 1024 + tid;
    int c = (i < N) ? cnt[i] : 0;
    if (i < N) dinv[i] = rsqrtf((float)c + 1.0f);
    int x = c;
    #pragma unroll
    for (int off = 1; off < 32; off <<= 1) {
        int y = __shfl_up_sync(0xffffffffu, x, off);
        if (lane >= off) x += y;
    }
    if (lane == 31) wsum[wid] = x;
    __syncthreads();
    if (wid == 0) {
        int w = wsum[lane];
        #pragma unroll
        for (int off = 1; off < 32; off <<= 1) {
            int y = __shfl_up_sync(0xffffffffu, w, off);
            if (lane >= off) w += y;
        }
        wsum[lane] = w;
    }
    __syncthreads();
    int incl = x + ((wid > 0) ? wsum[wid - 1] : 0);
    if (i < N) rowstart[i + 1] = incl;
    if (tid == 1023) bsum[blockIdx.x] = incl;
}

__global__ void scan2_k(const int* __restrict__ bsum, int* __restrict__ boff,
                        int* __restrict__ rowstart)
{
    __shared__ int s[64];
    int t = threadIdx.x;
    int x = (t < SCAN_NB) ? bsum[t] : 0;
    s[t] = x;
    __syncthreads();
    #pragma unroll
    for (int off = 1; off < 64; off <<= 1) {
        int y = (t >= off) ? s[t - off] : 0;
        __syncthreads();
        s[t] += y;
        __syncthreads();
    }
    boff[t] = s[t] - x;
    if (t == 0) rowstart[0] = 0;
}

__global__ void scan3_k(int* __restrict__ rowstart, const int* __restrict__ boff, int N)
{
    int i = blockIdx.x * 1024 + threadIdx.x;
    if (i < N) rowstart[i + 1] += boff[blockIdx.x];
}

__global__ void fill_k(const int* __restrict__ ei, int E,
                       const int* __restrict__ rowstart,
                       int* __restrict__ fill, int* __restrict__ csrc)
{
    int e = blockIdx.x * blockDim.x + threadIdx.x;
    if (e >= E) return;
    int is64 = g_is64;
    int s = edge_at(ei, is64, e);
    int d = edge_at(ei, is64, E + e);
    if ((unsigned)s >= (unsigned)N_NODES || (unsigned)d >= (unsigned)N_NODES)
        return;
    int pos = rowstart[d] + atomicAdd(&fill[d], 1);
    csrc[pos] = s;
}

// ---------------------------------------------------------------------------
// GCN aggregation: warp per dst node, fp16 in, fp32 math, fp16 out.
// ---------------------------------------------------------------------------
__global__ __launch_bounds__(256)
void gather_k(const int* __restrict__ rowstart, const int* __restrict__ csrc,
              const float* __restrict__ dinv, const __half* __restrict__ zw,
              const float* __restrict__ bias, __half* __restrict__ xcat,
              int N, int coloff)
{
    int d = blockIdx.x * (blockDim.x >> 5) + (threadIdx.x >> 5);
    if (d >= N) return;
    int lane = threadIdx.x & 31;
    int beg = rowstart[d], end = rowstart[d + 1];

    float ax = 0.f, ay = 0.f, az = 0.f, aw = 0.f;
    const uint2* zw2 = (const uint2*)zw;

    int j = beg;
    for (; j + 4 <= end; j += 4) {
        int s0 = __ldg(&csrc[j]);
        int s1 = __ldg(&csrc[j + 1]);
        int s2 = __ldg(&csrc[j + 2]);
        int s3 = __ldg(&csrc[j + 3]);
        float c0 = __ldg(&dinv[s0]);
        float c1 = __ldg(&dinv[s1]);
        float c2 = __ldg(&dinv[s2]);
        float c3 = __ldg(&dinv[s3]);
        uint2 v0 = __ldg(zw2 + (size_t)s0 * 32 + lane);
        uint2 v1 = __ldg(zw2 + (size_t)s1 * 32 + lane);
        uint2 v2 = __ldg(zw2 + (size_t)s2 * 32 + lane);
        uint2 v3 = __ldg(zw2 + (size_t)s3 * 32 + lane);
        float2 l0 = __half22float2(*(const __half2*)&v0.x), h0 = __half22float2(*(const __half2*)&v0.y);
        float2 l1 = __half22float2(*(const __half2*)&v1.x), h1 = __half22float2(*(const __half2*)&v1.y);
        float2 l2 = __half22float2(*(const __half2*)&v2.x), h2 = __half22float2(*(const __half2*)&v2.y);
        float2 l3 = __half22float2(*(const __half2*)&v3.x), h3 = __half22float2(*(const __half2*)&v3.y);
        ax += l0.x * c0 + l1.x * c1 + l2.x * c2 + l3.x * c3;
        ay += l0.y * c0 + l1.y * c1 + l2.y * c2 + l3.y * c3;
        az += h0.x * c0 + h1.x * c1 + h2.x * c2 + h3.x * c3;
        aw += h0.y * c0 + h1.y * c1 + h2.y * c2 + h3.y * c3;
    }
    for (; j < end; j++) {
        int s = __ldg(&csrc[j]);
        float c = __ldg(&dinv[s]);
        uint2 v = __ldg(zw2 + (size_t)s * 32 + lane);
        float2 lo = __half22float2(*(const __half2*)&v.x);
        float2 hi = __half22float2(*(const __half2*)&v.y);
        ax += lo.x * c; ay += lo.y * c; az += hi.x * c; aw += hi.y * c;
    }

    float dd = dinv[d];
    float s2 = dd * dd;
    uint2 sv = __ldg(zw2 + (size_t)d * 32 + lane);
    float2 slo = __half22float2(*(const __half2*)&sv.x);
    float2 shi = __half22float2(*(const __half2*)&sv.y);
    float4 b = ((const float4*)bias)[lane];
    __half2 o0 = __floats2half2_rn(fmaxf(ax * dd + slo.x * s2 + b.x, 0.f),
                                   fmaxf(ay * dd + slo.y * s2 + b.y, 0.f));
    __half2 o1 = __floats2half2_rn(fmaxf(az * dd + shi.x * s2 + b.z, 0.f),
                                   fmaxf(aw * dd + shi.y * s2 + b.w, 0.f));
    *(uint2*)(xcat + (size_t)d * 384 + coloff + lane * 4) =
        make_uint2(*(uint32_t*)&o0, *(uint32_t*)&o1);
}

// ---------------------------------------------------------------------------
// actor layer 2: out[M,10] = q1[M,256] @ w2[256,10] + b2  (warp per row)
// ---------------------------------------------------------------------------
__global__ __launch_bounds__(256)
void actor2_k(const __half* __restrict__ q1, const float* __restrict__ w2,
              const float* __restrict__ b2, float* __restrict__ out, int M)
{
    int row = blockIdx.x * (blockDim.x >> 5) + (threadIdx.x >> 5);
    if (row >= M) return;
    int lane = threadIdx.x & 31;
    float acc[10];
    #pragma unroll
    for (int c = 0; c < 10; c++) acc[c] = 0.f;
    const __half* qr = q1 + (size_t)row * 256;
    for (int k = lane; k < 256; k += 32) {
        float a = __half2float(qr[k]);
        const float* wr = w2 + k * 10;
        #pragma unroll
        for (int c = 0; c < 10; c++) acc[c] += a * wr[c];
    }
    #pragma unroll
    for (int c = 0; c < 10; c++) {
        #pragma unroll
        for (int off = 16; off; off >>= 1)
            acc[c] += __shfl_xor_sync(0xffffffffu, acc[c], off);
    }
    if (lane == 0) {
        #pragma unroll
        for (int c = 0; c < 10; c++)
            out[(size_t)row * 10 + c] = acc[c] + b2[c];
    }
}

// ---------------------------------------------------------------------------
extern "C" void kernel_launch(void* const* d_in, const int* in_sizes, int n_in,
                              void* d_out, int out_size)
{
    const float* x    = (const float*)d_in[0];
    const int*   ei   = (const int*)d_in[1];
    const float* e0w1 = (const float*)d_in[3];
    const float* e0b1 = (const float*)d_in[4];
    const float* e0w2 = (const float*)d_in[5];
    const float* e0b2 = (const float*)d_in[6];
    const float* e1w1 = (const float*)d_in[7];
    const float* e1b1 = (const float*)d_in[8];
    const float* e1w2 = (const float*)d_in[9];
    const float* e1b2 = (const float*)d_in[10];
    const float* gw[3] = {(const float*)d_in[11], (const float*)d_in[13], (const float*)d_in[15]};
    const float* gb[3] = {(const float*)d_in[12], (const float*)d_in[14], (const float*)d_in[16]};
    const float* aw1  = (const float*)d_in[17];
    const float* ab1  = (const float*)d_in[18];
    const float* aw2  = (const float*)d_in[19];
    const float* ab2  = (const float*)d_in[20];

    const int N  = N_NODES;
    const int E  = E_EDGES;
    const int NA = N_AGENT;

    __half *xh, *th, *hh, *zwh, *xcath, *q1h, *wt;
    float *dinv;
    int *cnt, *fill, *rowstart, *csrc, *bsum, *boff;
    cudaGetSymbolAddress((void**)&xh,       g_xh);
    cudaGetSymbolAddress((void**)&th,       g_th);
    cudaGetSymbolAddress((void**)&hh,       g_hh);
    cudaGetSymbolAddress((void**)&zwh,      g_zwh);
    cudaGetSymbolAddress((void**)&xcath,    g_xcath);
    cudaGetSymbolAddress((void**)&q1h,      g_q1h);
    cudaGetSymbolAddress((void**)&wt,       g_wt);
    cudaGetSymbolAddress((void**)&dinv,     g_dinv);
    cudaGetSymbolAddress((void**)&cnt,      g_cnt);
    cudaGetSymbolAddress((void**)&fill,     g_fill);
    cudaGetSymbolAddress((void**)&rowstart, g_rowstart);
    cudaGetSymbolAddress((void**)&csrc,     g_csrc);
    cudaGetSymbolAddress((void**)&bsum,     g_bsum);
    cudaGetSymbolAddress((void**)&boff,     g_boff);

    // dynamic smem opt-in (46080 fits default, setattr harmless)
    cudaFuncSetAttribute(hgemm_k<0>,  cudaFuncAttributeMaxDynamicSharedMemorySize, GSMEM);
    cudaFuncSetAttribute(hgemm_k<2>,  cudaFuncAttributeMaxDynamicSharedMemorySize, GSMEM);
    cudaFuncSetAttribute(hgemm2_k<1>, cudaFuncAttributeMaxDynamicSharedMemorySize, GSMEM);
    cudaFuncSetAttribute(hgemm2_k<2>, cudaFuncAttributeMaxDynamicSharedMemorySize, GSMEM);

    static cudaStream_t sCsr = nullptr;
    static cudaEvent_t  evFork = nullptr, evJoin = nullptr;
    if (!sCsr) {
        cudaStreamCreateWithFlags(&sCsr, cudaStreamNonBlocking);
        cudaEventCreateWithFlags(&evFork, cudaEventDisableTiming);
        cudaEventCreateWithFlags(&evJoin, cudaEventDisableTiming);
    }

    const int nbyA = (NA + 127) / 128;      // 196 blocks per segment
    dim3 gE(2, 2 * nbyA);                   // merged encoder: 784 blocks
    dim3 gN(2, (N + 127) / 128);            // 782 blocks
    dim3 gQ(4, nbyA);                       // 784 blocks

    // ---- fork: CSR branch on sCsr, encoder branch on default stream ----
    cudaEventRecord(evFork, 0);
    cudaStreamWaitEvent(sCsr, evFork, 0);

    detect_k<<<1, 32, 0, sCsr>>>(ei);
    cudaMemsetAsync(cnt,  0, N * sizeof(int), sCsr);
    cudaMemsetAsync(fill, 0, N * sizeof(int), sCsr);
    hist_k<<<(E + 255) / 256, 256, 0, sCsr>>>(ei, E, cnt);
    scan1_k<<<SCAN_NB, 1024, 0, sCsr>>>(cnt, rowstart, bsum, dinv, N);
    scan2_k<<<1, 64, 0, sCsr>>>(bsum, boff, rowstart);
    scan3_k<<<SCAN_NB, 1024, 0, sCsr>>>(rowstart, boff, N);
    fill_k<<<(E + 255) / 256, 256, 0, sCsr>>>(ei, E, rowstart, fill, csrc);
    cudaEventRecord(evJoin, sCsr);

    // encoder branch (default stream)
    f2h_k<<<(N * 128 / 4 + 255) / 256, 256>>>(x, xh, N * 128);
    wconv_k<<<(WT_TOTAL + 255) / 256, 256>>>(e0w1, e1w1, e0w2, e1w2,
                                             gw[0], gw[1], gw[2], aw1, wt);
    hgemm2_k<2><<<gE, 256, GSMEM>>>(xh, 128, wt + WT_E0W1, wt + WT_E1W1, 128, 64,
                                    e0b1, e1b1, th, 128, nbyA, NA, N);
    hgemm2_k<1><<<gE, 256, GSMEM>>>(th, 128, wt + WT_E0W2, wt + WT_E1W2, 128, 128,
                                    e0b2, e1b2, hh, 128, nbyA, NA, N);
    hgemm_k<0><<<gN, 256, GSMEM>>>(hh, 128, wt + WT_GW0, N, 128, 128, nullptr, zwh, 128);

    // ---- join: gathers need dinv/csrc (CSR) and zwh (encoder) ----
    cudaStreamWaitEvent(0, evJoin, 0);

    // GCN layers
    gather_k<<<(N * 32 + 255) / 256, 256>>>(rowstart, csrc, dinv, zwh, gb[0], xcath, N, 0);
    hgemm_k<0><<<gN, 256, GSMEM>>>(xcath, 384, wt + WT_GW1, N, 128, 128, nullptr, zwh, 128);
    gather_k<<<(N * 32 + 255) / 256, 256>>>(rowstart, csrc, dinv, zwh, gb[1], xcath, N, 128);
    hgemm_k<0><<<gN, 256, GSMEM>>>(xcath + 128, 384, wt + WT_GW2, N, 128, 128, nullptr, zwh, 128);
    gather_k<<<(N * 32 + 255) / 256, 256>>>(rowstart, csrc, dinv, zwh, gb[2], xcath, N, 256);

    // actor MLP
    hgemm_k<2><<<gQ, 256, GSMEM>>>(xcath, 384, wt + WT_AW1, NA, 256, 384, ab1, q1h, 256);
    actor2_k<<<(NA + 7) / 8, 256>>>(q1h, aw2, ab2, (float*)d_out, NA);
}

// round 15
// speedup vs baseline: 1.1220x; 1.1220x over previous
#include <cuda_runtime.h>
#include <cuda_fp16.h>
#include <cstdint>
#include <cstddef>

// ---------------------------------------------------------------------------
// HeteroMAGNet: fp16-native pipeline, cp.async double-buffered GEMMs.
// R15: GEMM geometry reverted to R12 optimum (BM128/BN64/KC64/2-stage).
//      New schedule-level wins:
//        * gather2 trimmed to NA rows (rows >= 25000 of layer-2 are dead)
//        * gather l / proj l+1 split into row halves on 2 streams ->
//          projA overlaps gatherB at each of the 2 layer boundaries.
// ---------------------------------------------------------------------------

#define N_NODES 50000
#define N_AGENT 25000
#define E_EDGES 800000
#define SCAN_NB 49   // ceil(50000/1024)
#define HALF_ROWS 25088   // 196 blocks * 128 (row split point)

// scratch (device globals: allocation-free)
__device__ __half g_xh[(size_t)N_NODES * 128];
__device__ __half g_th[(size_t)N_NODES * 128];
__device__ __half g_hh[(size_t)N_NODES * 128];
__device__ __half g_zwh[(size_t)N_NODES * 128];
__device__ __half g_xcath[(size_t)N_NODES * 384];
__device__ __half g_q1h[(size_t)N_AGENT * 256];
__device__ __half g_wt[204800];                  // all weights, fp16, [N][K]
__device__ float  g_dinv[N_NODES];
__device__ int    g_cnt[N_NODES];
__device__ int    g_fill[N_NODES];
__device__ int    g_rowstart[N_NODES + 1];
__device__ int    g_csrc[E_EDGES];
__device__ int    g_bsum[64];
__device__ int    g_boff[64];
__device__ int    g_is64;

// weight table offsets (halves) in g_wt
#define WT_E0W1 0        // K=128 N=128
#define WT_E1W1 16384    // K=64  N=128
#define WT_E0W2 24576    // K=128 N=128
#define WT_E1W2 40960    // K=128 N=128
#define WT_GW0  57344    // K=128 N=128
#define WT_GW1  73728
#define WT_GW2  90112
#define WT_AW1  106496   // K=384 N=256
#define WT_TOTAL 204800

// ---------------------------------------------------------------------------
// edge_index dtype detection (int64 vs harness-downcast int32)
// ---------------------------------------------------------------------------
__global__ void detect_k(const int* __restrict__ ei)
{
    int lane = threadIdx.x;
    int bad = 0;
    #pragma unroll
    for (int i = lane; i < 256; i += 32)
        if (ei[2 * i + 1] != 0) bad = 1;
    unsigned m = __ballot_sync(0xffffffffu, bad);
    if (lane == 0) g_is64 = (m == 0);
}

__device__ __forceinline__ int edge_at(const int* ei, int is64, int flat_idx)
{
    return is64 ? ei[2 * flat_idx] : ei[flat_idx];
}

// ---------------------------------------------------------------------------
// fp32 -> fp16 elementwise (n % 4 == 0)
// ---------------------------------------------------------------------------
__global__ void f2h_k(const float* __restrict__ src, __half* __restrict__ dst, int n)
{
    int i = (blockIdx.x * blockDim.x + threadIdx.x) * 4;
    if (i >= n) return;
    float4 v = *(const float4*)(src + i);
    __half2 h0 = __floats2half2_rn(v.x, v.y);
    __half2 h1 = __floats2half2_rn(v.z, v.w);
    *(uint2*)(dst + i) = make_uint2(*(uint32_t*)&h0, *(uint32_t*)&h1);
}

// ---------------------------------------------------------------------------
// all weights: transpose [K][N] -> [N][K] + convert to fp16, one kernel
// ---------------------------------------------------------------------------
__global__ void wconv_k(const float* __restrict__ w0, const float* __restrict__ w1,
                        const float* __restrict__ w2, const float* __restrict__ w3,
                        const float* __restrict__ w4, const float* __restrict__ w5,
                        const float* __restrict__ w6, const float* __restrict__ w7,
                        __half* __restrict__ wt)
{
    int i = blockIdx.x * blockDim.x + threadIdx.x;
    if (i >= WT_TOTAL) return;
    const float* w; int off, K, N;
    if      (i < WT_E1W1) { w = w0; off = WT_E0W1; K = 128; N = 128; }
    else if (i < WT_E0W2) { w = w1; off = WT_E1W1; K = 64;  N = 128; }
    else if (i < WT_E1W2) { w = w2; off = WT_E0W2; K = 128; N = 128; }
    else if (i < WT_GW0)  { w = w3; off = WT_E1W2; K = 128; N = 128; }
    else if (i < WT_GW1)  { w = w4; off = WT_GW0;  K = 128; N = 128; }
    else if (i < WT_GW2)  { w = w5; off = WT_GW1;  K = 128; N = 128; }
    else if (i < WT_AW1)  { w = w6; off = WT_GW2;  K = 128; N = 128; }
    else                  { w = w7; off = WT_AW1;  K = 384; N = 256; }
    int local = i - off;
    int n = local / K, k = local % K;
    wt[i] = __float2half(w[(size_t)k * N + n]);
}

// ---------------------------------------------------------------------------
// fp16 m16n8k16 MMA + ldmatrix + cp.async helpers
// ---------------------------------------------------------------------------
__device__ __forceinline__ void mma_f16(float& d0, float& d1, float& d2, float& d3,
                                        uint32_t a0, uint32_t a1, uint32_t a2, uint32_t a3,
                                        uint32_t b0, uint32_t b1)
{
    asm volatile(
        "mma.sync.aligned.m16n8k16.row.col.f32.f16.f16.f32 "
        "{%0,%1,%2,%3}, {%4,%5,%6,%7}, {%8,%9}, {%0,%1,%2,%3};\n"
        : "+f"(d0), "+f"(d1), "+f"(d2), "+f"(d3)
        : "r"(a0), "r"(a1), "r"(a2), "r"(a3), "r"(b0), "r"(b1));
}

__device__ __forceinline__ void ldsm4(uint32_t& r0, uint32_t& r1, uint32_t& r2, uint32_t& r3,
                                      uint32_t addr)
{
    asm volatile("ldmatrix.sync.aligned.m8n8.x4.shared.b16 {%0,%1,%2,%3}, [%4];"
                 : "=r"(r0), "=r"(r1), "=r"(r2), "=r"(r3) : "r"(addr));
}

__device__ __forceinline__ uint32_t smem_u32(const void* p)
{
    uint32_t a;
    asm("{ .reg .u64 t; cvta.to.shared.u64 t, %1; cvt.u32.u64 %0, t; }" : "=r"(a) : "l"(p));
    return a;
}

__device__ __forceinline__ void cp16(uint32_t dst, const void* src, int src_bytes)
{
    asm volatile("cp.async.cg.shared.global [%0], [%1], 16, %2;"
                 :: "r"(dst), "l"(src), "r"(src_bytes) : "memory");
}
#define CP_COMMIT() asm volatile("cp.async.commit_group;" ::: "memory")
#define CP_WAIT(n)  asm volatile("cp.async.wait_group %0;" :: "n"(n) : "memory")

// ---------------------------------------------------------------------------
// GEMM tile geometry (R12 optimum): BM=128, BN=64, KC=64, 2-stage cp.async.
// smem stride 72 halves (144B): LDSM rows hit distinct 16B segs mod 128B.
// Stage = A[128][72] + B[64][72] halves = 27648B; 2 stages = 55296B dynamic.
// 256 thr, warps 4(m) x 2(n), warp tile 32x32.
// ---------------------------------------------------------------------------
#define KC      64
#define GSTR    72
#define STAGE_B 27648
#define AB_OFF  18432
#define GSMEM   (2 * STAGE_B)

template <int EPI>
__device__ __forceinline__ void gemm_core(
    const __half* __restrict__ A, int lda, int bm, int rlimit,
    const __half* __restrict__ Bt, int bn, int K,
    const float* __restrict__ bias,
    __half* __restrict__ C, int ldc, int wlimit)
{
    extern __shared__ __half sm[];
    uint32_t sm_base = smem_u32(sm);
    int tid = threadIdx.x;
    int wid = tid >> 5, lane = tid & 31;
    int wm = wid >> 1, wn = wid & 1;
    int g = lane >> 2, q = lane & 3;

    float acc[2][4][4];
    #pragma unroll
    for (int i = 0; i < 2; i++)
        #pragma unroll
        for (int j = 0; j < 4; j++)
            #pragma unroll
            for (int k = 0; k < 4; k++) acc[i][j][k] = 0.f;

    auto load_stage = [&](int s, int k0) {
        uint32_t abase = sm_base + s * STAGE_B;
        #pragma unroll
        for (int j = 0; j < 4; j++) {            // A: 128 rows x 8 vec
            int v = tid + 256 * j;
            int row = v >> 3, col = (v & 7) * 8;
            const __half* src = A + (size_t)(bm + row) * lda + k0 + col;
            cp16(abase + (uint32_t)(row * GSTR + col) * 2, src,
                 (bm + row < rlimit) ? 16 : 0);
        }
        uint32_t bbase = abase + AB_OFF;
        #pragma unroll
        for (int j = 0; j < 2; j++) {            // B: 64 rows x 8 vec
            int v = tid + 256 * j;
            int row = v >> 3, col = (v & 7) * 8;
            const __half* src = Bt + (size_t)(bn + row) * K + k0 + col;
            cp16(bbase + (uint32_t)(row * GSTR + col) * 2, src, 16);
        }
        CP_COMMIT();
    };

    const int a_lrow = wm * 32 + (lane & 7) + ((lane >> 3) & 1) * 8;
    const int a_lcol = (lane >> 4) * 8;
    const int b_mat  = lane >> 3;
    const int b_lrow = wn * 32 + (b_mat >> 1) * 8 + (lane & 7);
    const int b_lcol = (b_mat & 1) * 8;

    const int NC = (K + KC - 1) / KC;
    load_stage(0, 0);

    for (int c = 0; c < NC; c++) {
        if (c + 1 < NC) {
            load_stage((c + 1) & 1, (c + 1) * KC);
            CP_WAIT(1);
        } else {
            CP_WAIT(0);
        }
        __syncthreads();

        uint32_t a_base = sm_base + (c & 1) * STAGE_B;
        uint32_t b_base = a_base + AB_OFF;

        #pragma unroll
        for (int kk = 0; kk < KC; kk += 16) {
            uint32_t a[2][4], b[4][2];
            #pragma unroll
            for (int mt = 0; mt < 2; mt++) {
                uint32_t addr = a_base + (uint32_t)(((a_lrow + mt * 16) * GSTR) + kk + a_lcol) * 2;
                ldsm4(a[mt][0], a[mt][1], a[mt][2], a[mt][3], addr);
            }
            #pragma unroll
            for (int p = 0; p < 2; p++) {
                uint32_t addr = b_base + (uint32_t)(((b_lrow + p * 16) * GSTR) + kk + b_lcol) * 2;
                ldsm4(b[2*p][0], b[2*p][1], b[2*p+1][0], b[2*p+1][1], addr);
            }
            #pragma unroll
            for (int mt = 0; mt < 2; mt++)
                #pragma unroll
                for (int nt = 0; nt < 4; nt++)
                    mma_f16(acc[mt][nt][0], acc[mt][nt][1], acc[mt][nt][2], acc[mt][nt][3],
                            a[mt][0], a[mt][1], a[mt][2], a[mt][3],
                            b[nt][0], b[nt][1]);
        }
        __syncthreads();
    }

    #pragma unroll
    for (int mt = 0; mt < 2; mt++) {
        #pragma unroll
        for (int nt = 0; nt < 4; nt++) {
            int row0 = bm + wm * 32 + mt * 16 + g;
            int col  = bn + wn * 32 + nt * 8 + 2 * q;
            float bx = 0.f, by = 0.f;
            if (EPI >= 1) { bx = bias[col]; by = bias[col + 1]; }
            float v0 = acc[mt][nt][0] + bx, v1 = acc[mt][nt][1] + by;
            float v2 = acc[mt][nt][2] + bx, v3 = acc[mt][nt][3] + by;
            if (EPI == 2) {
                v0 = fmaxf(v0, 0.f); v1 = fmaxf(v1, 0.f);
                v2 = fmaxf(v2, 0.f); v3 = fmaxf(v3, 0.f);
            }
            if (row0 < wlimit)     *(__half2*)(C + (size_t)row0 * ldc + col)       = __floats2half2_rn(v0, v1);
            if (row0 + 8 < wlimit) *(__half2*)(C + (size_t)(row0 + 8) * ldc + col) = __floats2half2_rn(v2, v3);
        }
    }
}

// by0: row-block offset (for split launches)
template <int EPI>
__global__ __launch_bounds__(256)
void hgemm_k(const __half* __restrict__ A, int lda,
             const __half* __restrict__ Bt,
             int M, int N, int K,
             const float* __restrict__ bias,
             __half* __restrict__ C, int ldc, int by0)
{
    gemm_core<EPI>(A, lda, (blockIdx.y + by0) * 128, M, Bt, blockIdx.x * 64, K, bias, C, ldc, M);
}

template <int EPI>
__global__ __launch_bounds__(256)
void hgemm2_k(const __half* __restrict__ A, int lda,
              const __half* __restrict__ Bt0, const __half* __restrict__ Bt1,
              int K0, int K1,
              const float* __restrict__ b0, const float* __restrict__ b1,
              __half* __restrict__ C, int ldc, int nby0, int M0, int M1)
{
    int by = blockIdx.y;
    if (by < nby0) {
        gemm_core<EPI>(A, lda, by * 128, M1, Bt0, blockIdx.x * 64, K0, b0, C, ldc, M0);
    } else {
        gemm_core<EPI>(A, lda, M0 + (by - nby0) * 128, M1, Bt1, blockIdx.x * 64, K1, b1, C, ldc, M1);
    }
}

// ---------------------------------------------------------------------------
// CSR build
// ---------------------------------------------------------------------------
__global__ void hist_k(const int* __restrict__ ei, int E, int* __restrict__ cnt)
{
    int e = blockIdx.x * blockDim.x + threadIdx.x;
    if (e >= E) return;
    int d = edge_at(ei, g_is64, E + e);
    if ((unsigned)d < (unsigned)N_NODES)
        atomicAdd(&cnt[d], 1);
}

__global__ void scan1_k(const int* __restrict__ cnt, int* __restrict__ rowstart,
                        int* __restrict__ bsum, float* __restrict__ dinv, int N)
{
    __shared__ int wsum[32];
    int tid = threadIdx.x, lane = tid & 31, wid = tid >> 5;
    int i = blockIdx.x * 1024 + tid;
    int c = (i < N) ? cnt[i] : 0;
    if (i < N) dinv[i] = rsqrtf((float)c + 1.0f);
    int x = c;
    #pragma unroll
    for (int off = 1; off < 32; off <<= 1) {
        int y = __shfl_up_sync(0xffffffffu, x, off);
        if (lane >= off) x += y;
    }
    if (lane == 31) wsum[wid] = x;
    __syncthreads();
    if (wid == 0) {
        int w = wsum[lane];
        #pragma unroll
        for (int off = 1; off < 32; off <<= 1) {
            int y = __shfl_up_sync(0xffffffffu, w, off);
            if (lane >= off) w += y;
        }
        wsum[lane] = w;
    }
    __syncthreads();
    int incl = x + ((wid > 0) ? wsum[wid - 1] : 0);
    if (i < N) rowstart[i + 1] = incl;
    if (tid == 1023) bsum[blockIdx.x] = incl;
}

__global__ void scan2_k(const int* __restrict__ bsum, int* __restrict__ boff,
                        int* __restrict__ rowstart)
{
    __shared__ int s[64];
    int t = threadIdx.x;
    int x = (t < SCAN_NB) ? bsum[t] : 0;
    s[t] = x;
    __syncthreads();
    #pragma unroll
    for (int off = 1; off < 64; off <<= 1) {
        int y = (t >= off) ? s[t - off] : 0;
        __syncthreads();
        s[t] += y;
        __syncthreads();
    }
    boff[t] = s[t] - x;
    if (t == 0) rowstart[0] = 0;
}

__global__ void scan3_k(int* __restrict__ rowstart, const int* __restrict__ boff, int N)
{
    int i = blockIdx.x * 1024 + threadIdx.x;
    if (i < N) rowstart[i + 1] += boff[blockIdx.x];
}

__global__ void fill_k(const int* __restrict__ ei, int E,
                       const int* __restrict__ rowstart,
                       int* __restrict__ fill, int* __restrict__ csrc)
{
    int e = blockIdx.x * blockDim.x + threadIdx.x;
    if (e >= E) return;
    int is64 = g_is64;
    int s = edge_at(ei, is64, e);
    int d = edge_at(ei, is64, E + e);
    if ((unsigned)s >= (unsigned)N_NODES || (unsigned)d >= (unsigned)N_NODES)
        return;
    int pos = rowstart[d] + atomicAdd(&fill[d], 1);
    csrc[pos] = s;
}

// ---------------------------------------------------------------------------
// GCN aggregation: warp per dst node in [d0, dend), fp16 in/out, fp32 math.
// ---------------------------------------------------------------------------
__global__ __launch_bounds__(256)
void gather_k(const int* __restrict__ rowstart, const int* __restrict__ csrc,
              const float* __restrict__ dinv, const __half* __restrict__ zw,
              const float* __restrict__ bias, __half* __restrict__ xcat,
              int d0, int dend, int coloff)
{
    int d = d0 + blockIdx.x * (blockDim.x >> 5) + (threadIdx.x >> 5);
    if (d >= dend) return;
    int lane = threadIdx.x & 31;
    int beg = rowstart[d], end = rowstart[d + 1];

    float ax = 0.f, ay = 0.f, az = 0.f, aw = 0.f;
    const uint2* zw2 = (const uint2*)zw;

    int j = beg;
    for (; j + 4 <= end; j += 4) {
        int s0 = __ldg(&csrc[j]);
        int s1 = __ldg(&csrc[j + 1]);
        int s2 = __ldg(&csrc[j + 2]);
        int s3 = __ldg(&csrc[j + 3]);
        float c0 = __ldg(&dinv[s0]);
        float c1 = __ldg(&dinv[s1]);
        float c2 = __ldg(&dinv[s2]);
        float c3 = __ldg(&dinv[s3]);
        uint2 v0 = __ldg(zw2 + (size_t)s0 * 32 + lane);
        uint2 v1 = __ldg(zw2 + (size_t)s1 * 32 + lane);
        uint2 v2 = __ldg(zw2 + (size_t)s2 * 32 + lane);
        uint2 v3 = __ldg(zw2 + (size_t)s3 * 32 + lane);
        float2 l0 = __half22float2(*(const __half2*)&v0.x), h0 = __half22float2(*(const __half2*)&v0.y);
        float2 l1 = __half22float2(*(const __half2*)&v1.x), h1 = __half22float2(*(const __half2*)&v1.y);
        float2 l2 = __half22float2(*(const __half2*)&v2.x), h2 = __half22float2(*(const __half2*)&v2.y);
        float2 l3 = __half22float2(*(const __half2*)&v3.x), h3 = __half22float2(*(const __half2*)&v3.y);
        ax += l0.x * c0 + l1.x * c1 + l2.x * c2 + l3.x * c3;
        ay += l0.y * c0 + l1.y * c1 + l2.y * c2 + l3.y * c3;
        az += h0.x * c0 + h1.x * c1 + h2.x * c2 + h3.x * c3;
        aw += h0.y * c0 + h1.y * c1 + h2.y * c2 + h3.y * c3;
    }
    for (; j < end; j++) {
        int s = __ldg(&csrc[j]);
        float c = __ldg(&dinv[s]);
        uint2 v = __ldg(zw2 + (size_t)s * 32 + lane);
        float2 lo = __half22float2(*(const __half2*)&v.x);
        float2 hi = __half22float2(*(const __half2*)&v.y);
        ax += lo.x * c; ay += lo.y * c; az += hi.x * c; aw += hi.y * c;
    }

    float dd = dinv[d];
    float s2 = dd * dd;
    uint2 sv = __ldg(zw2 + (size_t)d * 32 + lane);
    float2 slo = __half22float2(*(const __half2*)&sv.x);
    float2 shi = __half22float2(*(const __half2*)&sv.y);
    float4 b = ((const float4*)bias)[lane];
    __half2 o0 = __floats2half2_rn(fmaxf(ax * dd + slo.x * s2 + b.x, 0.f),
                                   fmaxf(ay * dd + slo.y * s2 + b.y, 0.f));
    __half2 o1 = __floats2half2_rn(fmaxf(az * dd + shi.x * s2 + b.z, 0.f),
                                   fmaxf(aw * dd + shi.y * s2 + b.w, 0.f));
    *(uint2*)(xcat + (size_t)d * 384 + coloff + lane * 4) =
        make_uint2(*(uint32_t*)&o0, *(uint32_t*)&o1);
}

// ---------------------------------------------------------------------------
// actor layer 2: out[M,10] = q1[M,256] @ w2[256,10] + b2  (warp per row)
// ---------------------------------------------------------------------------
__global__ __launch_bounds__(256)
void actor2_k(const __half* __restrict__ q1, const float* __restrict__ w2,
              const float* __restrict__ b2, float* __restrict__ out, int M)
{
    int row = blockIdx.x * (blockDim.x >> 5) + (threadIdx.x >> 5);
    if (row >= M) return;
    int lane = threadIdx.x & 31;
    float acc[10];
    #pragma unroll
    for (int c = 0; c < 10; c++) acc[c] = 0.f;
    const __half* qr = q1 + (size_t)row * 256;
    for (int k = lane; k < 256; k += 32) {
        float a = __half2float(qr[k]);
        const float* wr = w2 + k * 10;
        #pragma unroll
        for (int c = 0; c < 10; c++) acc[c] += a * wr[c];
    }
    #pragma unroll
    for (int c = 0; c < 10; c++) {
        #pragma unroll
        for (int off = 16; off; off >>= 1)
            acc[c] += __shfl_xor_sync(0xffffffffu, acc[c], off);
    }
    if (lane == 0) {
        #pragma unroll
        for (int c = 0; c < 10; c++)
            out[(size_t)row * 10 + c] = acc[c] + b2[c];
    }
}

// ---------------------------------------------------------------------------
extern "C" void kernel_launch(void* const* d_in, const int* in_sizes, int n_in,
                              void* d_out, int out_size)
{
    const float* x    = (const float*)d_in[0];
    const int*   ei   = (const int*)d_in[1];
    const float* e0w1 = (const float*)d_in[3];
    const float* e0b1 = (const float*)d_in[4];
    const float* e0w2 = (const float*)d_in[5];
    const float* e0b2 = (const float*)d_in[6];
    const float* e1w1 = (const float*)d_in[7];
    const float* e1b1 = (const float*)d_in[8];
    const float* e1w2 = (const float*)d_in[9];
    const float* e1b2 = (const float*)d_in[10];
    const float* gw[3] = {(const float*)d_in[11], (const float*)d_in[13], (const float*)d_in[15]};
    const float* gb[3] = {(const float*)d_in[12], (const float*)d_in[14], (const float*)d_in[16]};
    const float* aw1  = (const float*)d_in[17];
    const float* ab1  = (const float*)d_in[18];
    const float* aw2  = (const float*)d_in[19];
    const float* ab2  = (const float*)d_in[20];

    const int N  = N_NODES;
    const int E  = E_EDGES;
    const int NA = N_AGENT;

    __half *xh, *th, *hh, *zwh, *xcath, *q1h, *wt;
    float *dinv;
    int *cnt, *fill, *rowstart, *csrc, *bsum, *boff;
    cudaGetSymbolAddress((void**)&xh,       g_xh);
    cudaGetSymbolAddress((void**)&th,       g_th);
    cudaGetSymbolAddress((void**)&hh,       g_hh);
    cudaGetSymbolAddress((void**)&zwh,      g_zwh);
    cudaGetSymbolAddress((void**)&xcath,    g_xcath);
    cudaGetSymbolAddress((void**)&q1h,      g_q1h);
    cudaGetSymbolAddress((void**)&wt,       g_wt);
    cudaGetSymbolAddress((void**)&dinv,     g_dinv);
    cudaGetSymbolAddress((void**)&cnt,      g_cnt);
    cudaGetSymbolAddress((void**)&fill,     g_fill);
    cudaGetSymbolAddress((void**)&rowstart, g_rowstart);
    cudaGetSymbolAddress((void**)&csrc,     g_csrc);
    cudaGetSymbolAddress((void**)&bsum,     g_bsum);
    cudaGetSymbolAddress((void**)&boff,     g_boff);

    cudaFuncSetAttribute(hgemm_k<0>,  cudaFuncAttributeMaxDynamicSharedMemorySize, GSMEM);
    cudaFuncSetAttribute(hgemm_k<2>,  cudaFuncAttributeMaxDynamicSharedMemorySize, GSMEM);
    cudaFuncSetAttribute(hgemm2_k<1>, cudaFuncAttributeMaxDynamicSharedMemorySize, GSMEM);
    cudaFuncSetAttribute(hgemm2_k<2>, cudaFuncAttributeMaxDynamicSharedMemorySize, GSMEM);

    static cudaStream_t s1 = nullptr;
    static cudaEvent_t evFork = nullptr, evJoin = nullptr, evP0 = nullptr;
    static cudaEvent_t evA1 = nullptr, evB1 = nullptr, evA2 = nullptr, evB2 = nullptr;
    if (!s1) {
        cudaStreamCreateWithFlags(&s1, cudaStreamNonBlocking);
        cudaEventCreateWithFlags(&evFork, cudaEventDisableTiming);
        cudaEventCreateWithFlags(&evJoin, cudaEventDisableTiming);
        cudaEventCreateWithFlags(&evP0,   cudaEventDisableTiming);
        cudaEventCreateWithFlags(&evA1,   cudaEventDisableTiming);
        cudaEventCreateWithFlags(&evB1,   cudaEventDisableTiming);
        cudaEventCreateWithFlags(&evA2,   cudaEventDisableTiming);
        cudaEventCreateWithFlags(&evB2,   cudaEventDisableTiming);
    }

    const int nbyA = (NA + 127) / 128;        // 196 row-blocks (rows < 25088)
    const int nbyN = (N + 127) / 128;         // 391
    const int nbyB = nbyN - nbyA;             // 195 (rows 25088..50000)
    dim3 gE(2, 2 * nbyA);                     // merged encoder: 784 blocks
    dim3 gN(2, nbyN);                         // full-N GEMM: 782 blocks
    dim3 gPA(2, nbyA), gPB(2, nbyB);          // split proj halves
    dim3 gQ(4, nbyA);                         // actor1: 784 blocks
    const int gGA = (HALF_ROWS * 32 + 255) / 256;          // gather A half
    const int gGB = ((N - HALF_ROWS) * 32 + 255) / 256;    // gather B half
    const int gG2 = (NA * 32 + 255) / 256;                 // gather2 (trimmed)

    // ---- fork: CSR branch on s1, encoder branch on default stream (s0) ----
    cudaEventRecord(evFork, 0);
    cudaStreamWaitEvent(s1, evFork, 0);

    detect_k<<<1, 32, 0, s1>>>(ei);
    cudaMemsetAsync(cnt,  0, N * sizeof(int), s1);
    cudaMemsetAsync(fill, 0, N * sizeof(int), s1);
    hist_k<<<(E + 255) / 256, 256, 0, s1>>>(ei, E, cnt);
    scan1_k<<<SCAN_NB, 1024, 0, s1>>>(cnt, rowstart, bsum, dinv, N);
    scan2_k<<<1, 64, 0, s1>>>(bsum, boff, rowstart);
    scan3_k<<<SCAN_NB, 1024, 0, s1>>>(rowstart, boff, N);
    fill_k<<<(E + 255) / 256, 256, 0, s1>>>(ei, E, rowstart, fill, csrc);
    cudaEventRecord(evJoin, s1);

    // encoder branch (s0)
    f2h_k<<<(N * 128 / 4 + 255) / 256, 256>>>(x, xh, N * 128);
    wconv_k<<<(WT_TOTAL + 255) / 256, 256>>>(e0w1, e1w1, e0w2, e1w2,
                                             gw[0], gw[1], gw[2], aw1, wt);
    hgemm2_k<2><<<gE, 256, GSMEM>>>(xh, 128, wt + WT_E0W1, wt + WT_E1W1, 128, 64,
                                    e0b1, e1b1, th, 128, nbyA, NA, N);
    hgemm2_k<1><<<gE, 256, GSMEM>>>(th, 128, wt + WT_E0W2, wt + WT_E1W2, 128, 128,
                                    e0b2, e1b2, hh, 128, nbyA, NA, N);
    hgemm_k<0><<<gN, 256, GSMEM>>>(hh, 128, wt + WT_GW0, N, 128, 128, nullptr, zwh, 128, 0);
    cudaEventRecord(evP0, 0);

    // ---- join CSR into s0; s1 gets proj0 visibility ----
    cudaStreamWaitEvent(0, evJoin, 0);
    cudaStreamWaitEvent(s1, evP0, 0);
    // (s1 already has CSR results in-stream)

    // ---- layer 0 gather + layer 1 proj, split row halves across streams ----
    gather_k<<<gGA, 256>>>(rowstart, csrc, dinv, zwh, gb[0], xcath, 0, HALF_ROWS, 0);
    gather_k<<<gGB, 256, 0, s1>>>(rowstart, csrc, dinv, zwh, gb[0], xcath, HALF_ROWS, N, 0);
    hgemm_k<0><<<gPA, 256, GSMEM>>>(xcath, 384, wt + WT_GW1, HALF_ROWS, 128, 128, nullptr, zwh, 128, 0);
    hgemm_k<0><<<gPB, 256, GSMEM, s1>>>(xcath, 384, wt + WT_GW1, N, 128, 128, nullptr, zwh, 128, nbyA);
    cudaEventRecord(evA1, 0);
    cudaEventRecord(evB1, s1);
    cudaStreamWaitEvent(0, evB1, 0);
    cudaStreamWaitEvent(s1, evA1, 0);

    // ---- layer 1 gather + layer 2 proj ----
    gather_k<<<gGA, 256>>>(rowstart, csrc, dinv, zwh, gb[1], xcath, 0, HALF_ROWS, 128);
    gather_k<<<gGB, 256, 0, s1>>>(rowstart, csrc, dinv, zwh, gb[1], xcath, HALF_ROWS, N, 128);
    hgemm_k<0><<<gPA, 256, GSMEM>>>(xcath + 128, 384, wt + WT_GW2, HALF_ROWS, 128, 128, nullptr, zwh, 128, 0);
    hgemm_k<0><<<gPB, 256, GSMEM, s1>>>(xcath + 128, 384, wt + WT_GW2, N, 128, 128, nullptr, zwh, 128, nbyA);
    cudaEventRecord(evA2, 0);
    cudaEventRecord(evB2, s1);
    cudaStreamWaitEvent(0, evB2, 0);

    // ---- layer 2 gather (only agent rows are live) + actor MLP ----
    gather_k<<<gG2, 256>>>(rowstart, csrc, dinv, zwh, gb[2], xcath, 0, NA, 256);
    hgemm_k<2><<<gQ, 256, GSMEM>>>(xcath, 384, wt + WT_AW1, NA, 256, 384, ab1, q1h, 256, 0);
    actor2_k<<<(NA + 7) / 8, 256>>>(q1h, aw2, ab2, (float*)d_out, NA);
}